// round 8
// baseline (speedup 1.0000x reference)
#include <cuda_runtime.h>
#include <cstdint>

// Problem constants (fixed by the reference)
#define VOCAB 32000
#define D_EMB 768
#define SEQ   2048
#define BATCH 16
#define F4    (D_EMB / 4)       // 192 float4 per row
#define ROWS_PER_ITER 2
#define ITERS 2                  // each block does s-pairs {bid, bid+512}
#define GRID  (SEQ / (ROWS_PER_ITER * ITERS))   // 512
#define THREADS (F4 * ROWS_PER_ITER)            // 384

// ---------------------------------------------------------------------------
// Semantics (from the reference's where() inversion):
//   out[b,s,d] = pe[s,d]
//              + (input_ids[b,s]==0     ? W_tok[d,0]+b_tok[d] : 0)
//              + (segment_label[b,s]==0 ? W_seg[d,0]+b_seg[d] : 0)
//
// R6 change: grid halved to 512; each block handles TWO s-pairs (iterations),
// so the expensive strided prep gather (1536 isolated 32B sectors + a
// __syncthreads) is amortized 2x. 384 thr / 38 regs -> 4 blocks/SM -> 592
// concurrent CTAs >= 512: the whole grid is a single wave, no tail.
// ---------------------------------------------------------------------------
__global__ void __launch_bounds__(THREADS)
bebert_fused_kernel(const int*   __restrict__ input_ids,
                    const int*   __restrict__ segment_label,
                    const float* __restrict__ W_tok,
                    const float* __restrict__ b_tok,
                    const float* __restrict__ W_seg,
                    const float* __restrict__ b_seg,
                    const float* __restrict__ pe,
                    float*       __restrict__ out)
{
    __shared__ __align__(16) float s_tok[D_EMB];
    __shared__ __align__(16) float s_seg[D_EMB];
    __shared__ int s_mask[ITERS][ROWS_PER_ITER][BATCH];

    const int t = threadIdx.x;

    // --- prep: combined vectors into smem (2 elements per thread) ---
#pragma unroll
    for (int d = t; d < D_EMB; d += THREADS) {
        s_tok[d] = __ldg(W_tok + (size_t)d * VOCAB) + __ldg(b_tok + d);
        s_seg[d] = __ldg(W_seg + (size_t)d * 3)     + __ldg(b_seg + d);
    }

    // --- cooperative id -> mask load for BOTH iterations (64 threads) ---
    if (t < ITERS * ROWS_PER_ITER * BATCH) {
        const int iter  = t >> 5;          // 0..ITERS-1
        const int local = (t >> 4) & 1;    // row within pair
        const int b     = t & 15;          // batch index
        const int s     = blockIdx.x * ROWS_PER_ITER + local
                        + iter * (GRID * ROWS_PER_ITER);   // +1024 for iter 1
        const int row   = b * SEQ + s;
        s_mask[iter][local][b] =
              (__ldg(input_ids     + row) == 0 ? 1 : 0)
            | (__ldg(segment_label + row) == 0 ? 2 : 0);
    }
    __syncthreads();

    const int local = t / F4;              // 0..ROWS_PER_ITER-1
    const int c     = t % F4;              // float4 column within row

    const float4 tv = reinterpret_cast<const float4*>(s_tok)[c];
    const float4 sv = reinterpret_cast<const float4*>(s_seg)[c];

#pragma unroll
    for (int iter = 0; iter < ITERS; ++iter) {
        const int s = blockIdx.x * ROWS_PER_ITER + local
                    + iter * (GRID * ROWS_PER_ITER);

        const float4 p =
            reinterpret_cast<const float4*>(pe + (size_t)s * D_EMB)[c];

        float4* out4 = reinterpret_cast<float4*>(out) + (size_t)s * F4 + c;

#pragma unroll
        for (int b = 0; b < BATCH; ++b) {
            const int m = s_mask[iter][local][b];   // smem broadcast
            float4 r = p;
            if (m & 1) { r.x += tv.x; r.y += tv.y; r.z += tv.z; r.w += tv.w; }
            if (m & 2) { r.x += sv.x; r.y += sv.y; r.z += sv.z; r.w += sv.w; }
            out4[(size_t)b * (SEQ * F4)] = r;       // coalesced 512B per warp
        }
    }
}

// ---------------------------------------------------------------------------
// Launch. Input order (metadata): input_ids, segment_label, W_tok, b_tok,
// W_seg, b_seg, pe. ids arrive as int32 (jax x64 disabled). Output fp32.
// ---------------------------------------------------------------------------
extern "C" void kernel_launch(void* const* d_in, const int* in_sizes, int n_in,
                              void* d_out, int out_size) {
    const int*   input_ids     = (const int*)  d_in[0];
    const int*   segment_label = (const int*)  d_in[1];
    const float* W_tok         = (const float*)d_in[2];
    const float* b_tok         = (const float*)d_in[3];
    const float* W_seg         = (const float*)d_in[4];
    const float* b_seg         = (const float*)d_in[5];
    const float* pe            = (const float*)d_in[6];
    float*       out           = (float*)d_out;

    bebert_fused_kernel<<<GRID, THREADS>>>(
        input_ids, segment_label, W_tok, b_tok, W_seg, b_seg, pe, out);
}

// round 9
// speedup vs baseline: 1.0242x; 1.0242x over previous
#include <cuda_runtime.h>
#include <cstdint>

// Problem constants (fixed by the reference)
#define VOCAB 32000
#define D_EMB 768
#define SEQ   2048
#define BATCH 16
#define F4    (D_EMB / 4)       // 192 float4 per row
#define ROWS_PER_ITER 2
#define ITERS 2                  // each block does s-pairs {bid, bid+512}
#define GRID  (SEQ / (ROWS_PER_ITER * ITERS))   // 512
#define THREADS (F4 * ROWS_PER_ITER)            // 384

// ---------------------------------------------------------------------------
// Semantics (from the reference's where() inversion):
//   out[b,s,d] = pe[s,d]
//              + (input_ids[b,s]==0     ? W_tok[d,0]+b_tok[d] : 0)
//              + (segment_label[b,s]==0 ? W_seg[d,0]+b_seg[d] : 0)
//
// R6 change: grid halved to 512; each block handles TWO s-pairs (iterations),
// so the expensive strided prep gather (1536 isolated 32B sectors + a
// __syncthreads) is amortized 2x. 384 thr / 38 regs -> 4 blocks/SM -> 592
// concurrent CTAs >= 512: the whole grid is a single wave, no tail.
// ---------------------------------------------------------------------------
__global__ void __launch_bounds__(THREADS)
bebert_fused_kernel(const int*   __restrict__ input_ids,
                    const int*   __restrict__ segment_label,
                    const float* __restrict__ W_tok,
                    const float* __restrict__ b_tok,
                    const float* __restrict__ W_seg,
                    const float* __restrict__ b_seg,
                    const float* __restrict__ pe,
                    float*       __restrict__ out)
{
    __shared__ __align__(16) float s_tok[D_EMB];
    __shared__ __align__(16) float s_seg[D_EMB];
    __shared__ int s_mask[ITERS][ROWS_PER_ITER][BATCH];

    const int t = threadIdx.x;

    // --- prep: combined vectors into smem (2 elements per thread) ---
#pragma unroll
    for (int d = t; d < D_EMB; d += THREADS) {
        s_tok[d] = __ldg(W_tok + (size_t)d * VOCAB) + __ldg(b_tok + d);
        s_seg[d] = __ldg(W_seg + (size_t)d * 3)     + __ldg(b_seg + d);
    }

    // --- cooperative id -> mask load for BOTH iterations (64 threads) ---
    if (t < ITERS * ROWS_PER_ITER * BATCH) {
        const int iter  = t >> 5;          // 0..ITERS-1
        const int local = (t >> 4) & 1;    // row within pair
        const int b     = t & 15;          // batch index
        const int s     = blockIdx.x * ROWS_PER_ITER + local
                        + iter * (GRID * ROWS_PER_ITER);   // +1024 for iter 1
        const int row   = b * SEQ + s;
        s_mask[iter][local][b] =
              (__ldg(input_ids     + row) == 0 ? 1 : 0)
            | (__ldg(segment_label + row) == 0 ? 2 : 0);
    }
    __syncthreads();

    const int local = t / F4;              // 0..ROWS_PER_ITER-1
    const int c     = t % F4;              // float4 column within row

    const float4 tv = reinterpret_cast<const float4*>(s_tok)[c];
    const float4 sv = reinterpret_cast<const float4*>(s_seg)[c];

#pragma unroll
    for (int iter = 0; iter < ITERS; ++iter) {
        const int s = blockIdx.x * ROWS_PER_ITER + local
                    + iter * (GRID * ROWS_PER_ITER);

        const float4 p =
            reinterpret_cast<const float4*>(pe + (size_t)s * D_EMB)[c];

        float4* out4 = reinterpret_cast<float4*>(out) + (size_t)s * F4 + c;

#pragma unroll
        for (int b = 0; b < BATCH; ++b) {
            const int m = s_mask[iter][local][b];   // smem broadcast
            float4 r = p;
            if (m & 1) { r.x += tv.x; r.y += tv.y; r.z += tv.z; r.w += tv.w; }
            if (m & 2) { r.x += sv.x; r.y += sv.y; r.z += sv.z; r.w += sv.w; }
            out4[(size_t)b * (SEQ * F4)] = r;       // coalesced 512B per warp
        }
    }
}

// ---------------------------------------------------------------------------
// Launch. Input order (metadata): input_ids, segment_label, W_tok, b_tok,
// W_seg, b_seg, pe. ids arrive as int32 (jax x64 disabled). Output fp32.
// ---------------------------------------------------------------------------
extern "C" void kernel_launch(void* const* d_in, const int* in_sizes, int n_in,
                              void* d_out, int out_size) {
    const int*   input_ids     = (const int*)  d_in[0];
    const int*   segment_label = (const int*)  d_in[1];
    const float* W_tok         = (const float*)d_in[2];
    const float* b_tok         = (const float*)d_in[3];
    const float* W_seg         = (const float*)d_in[4];
    const float* b_seg         = (const float*)d_in[5];
    const float* pe            = (const float*)d_in[6];
    float*       out           = (float*)d_out;

    bebert_fused_kernel<<<GRID, THREADS>>>(
        input_ids, segment_label, W_tok, b_tok, W_seg, b_seg, pe, out);
}

// round 10
// speedup vs baseline: 1.2241x; 1.1951x over previous
#include <cuda_runtime.h>
#include <cstdint>

// Problem constants (fixed by the reference)
#define VOCAB 32000
#define D_EMB 768
#define SEQ   2048
#define BATCH 16
#define F4    (D_EMB / 4)        // 192 float4 per row

// Geometry: grid = (512, 3). blockIdx.x -> chunk of 4 s-rows,
// blockIdx.y -> one of 3 c-slices (64 float4 = 256 d values).
// 256 threads = 4 s-rows x 64 c-columns. Warp stores are 512B contiguous.
#define S_PER_BLK 4
#define C_PER_BLK 64             // float4 columns per block
#define D_PER_BLK (C_PER_BLK * 4) // 256
#define THREADS   (S_PER_BLK * C_PER_BLK) // 256

// ---------------------------------------------------------------------------
// Semantics (from the reference's where() inversion):
//   out[b,s,d] = pe[s,d]
//              + (input_ids[b,s]==0     ? W_tok[d,0]+b_tok[d] : 0)
//              + (segment_label[b,s]==0 ? W_seg[d,0]+b_seg[d] : 0)
//
// R9 -> R10 changes:
//  * D split across gridDim.y=3: per-block strided W_tok gather drops from
//    768 sectors to 256 (total prep L1 wavefronts halved vs the R5 champion).
//  * Masks packed via __ballot_sync into 4 uint32 words: one LDS pair per
//    worker thread instead of 16 serialized LDS->FADD->STG chains; per-store
//    mask check is a register bit test.
//  * 256 threads, low regs -> 8 blocks/SM, grid 1536 ~ one fat wave.
// ---------------------------------------------------------------------------
__global__ void __launch_bounds__(THREADS)
bebert_fused_kernel(const int*   __restrict__ input_ids,
                    const int*   __restrict__ segment_label,
                    const float* __restrict__ W_tok,
                    const float* __restrict__ b_tok,
                    const float* __restrict__ W_seg,
                    const float* __restrict__ b_seg,
                    const float* __restrict__ pe,
                    float*       __restrict__ out)
{
    __shared__ __align__(16) float s_tok[D_PER_BLK];
    __shared__ __align__(16) float s_seg[D_PER_BLK];
    // Packed predicate words: tokbits[w] / segbits[w] cover s-rows {2w, 2w+1},
    // bit layout: bit (r_in_pair*16 + b).
    __shared__ unsigned s_tokbits[2];
    __shared__ unsigned s_segbits[2];

    const int t      = threadIdx.x;
    const int s0     = blockIdx.x * S_PER_BLK;
    const int cslice = blockIdx.y;           // 0..2
    const int d0     = cslice * D_PER_BLK;   // first d of this slice

    // --- prep: combined vectors for this slice (1 element per thread) ---
    {
        const int d = d0 + t;                // t < 256 == D_PER_BLK
        s_tok[t] = __ldg(W_tok + (size_t)d * VOCAB) + __ldg(b_tok + d);
        s_seg[t] = __ldg(W_seg + (size_t)d * 3)     + __ldg(b_seg + d);
    }

    // --- masks via warp ballot: warps 0,1 each cover 2 s-rows x 16 b ---
    if (t < 64) {
        const int w = t >> 5;                // warp: rows {2w, 2w+1}
        const int l = t & 31;
        const int r = (w << 1) + (l >> 4);   // local s-row 0..3
        const int b = l & 15;
        const int row = b * SEQ + s0 + r;
        const unsigned tokv = __ballot_sync(0xFFFFFFFFu,
                                            __ldg(input_ids     + row) == 0);
        const unsigned segv = __ballot_sync(0xFFFFFFFFu,
                                            __ldg(segment_label + row) == 0);
        if (l == 0) { s_tokbits[w] = tokv; s_segbits[w] = segv; }
    }
    __syncthreads();

    const int local_s = t >> 6;              // 0..3
    const int c_local = t & 63;              // 0..63
    const int s       = s0 + local_s;
    const int c       = cslice * C_PER_BLK + c_local;

    const float4 tv = reinterpret_cast<const float4*>(s_tok)[c_local];
    const float4 sv = reinterpret_cast<const float4*>(s_seg)[c_local];
    const float4 p  = reinterpret_cast<const float4*>(pe + (size_t)s * D_EMB)[c];

    const unsigned tokw = s_tokbits[local_s >> 1] >> ((local_s & 1) << 4);
    const unsigned segw = s_segbits[local_s >> 1] >> ((local_s & 1) << 4);

    float4* out4 = reinterpret_cast<float4*>(out) + (size_t)s * F4 + c;

#pragma unroll
    for (int b = 0; b < BATCH; ++b) {
        float4 r = p;
        if ((tokw >> b) & 1u) { r.x += tv.x; r.y += tv.y; r.z += tv.z; r.w += tv.w; }
        if ((segw >> b) & 1u) { r.x += sv.x; r.y += sv.y; r.z += sv.z; r.w += sv.w; }
        out4[(size_t)b * (SEQ * F4)] = r;    // coalesced 512B per warp
    }
}

// ---------------------------------------------------------------------------
// Launch. Input order (metadata): input_ids, segment_label, W_tok, b_tok,
// W_seg, b_seg, pe. ids arrive as int32 (jax x64 disabled). Output fp32.
// ---------------------------------------------------------------------------
extern "C" void kernel_launch(void* const* d_in, const int* in_sizes, int n_in,
                              void* d_out, int out_size) {
    const int*   input_ids     = (const int*)  d_in[0];
    const int*   segment_label = (const int*)  d_in[1];
    const float* W_tok         = (const float*)d_in[2];
    const float* b_tok         = (const float*)d_in[3];
    const float* W_seg         = (const float*)d_in[4];
    const float* b_seg         = (const float*)d_in[5];
    const float* pe            = (const float*)d_in[6];
    float*       out           = (float*)d_out;

    dim3 grid(SEQ / S_PER_BLK, F4 / C_PER_BLK);   // (512, 3)
    bebert_fused_kernel<<<grid, THREADS>>>(
        input_ids, segment_label, W_tok, b_tok, W_seg, b_seg, pe, out);
}